// round 8
// baseline (speedup 1.0000x reference)
#include <cuda_runtime.h>

// Problem constants
#define N_IN   1024
#define N_OUT  1024
#define B_TOT  32
#define TPB    256            // threads per block; each thread owns 4 consecutive o's
#define NCH    32             // number of i-chunks (grid sized for HBM saturation: 256 CTAs)
#define CHUNK  (N_IN / NCH)   // 32 i's per chunk
#define BG     4              // batches per block (W register reuse across batches)
#define BGRP   (B_TOT / BG)   // 8 batch groups

// Deterministic partial buffer: [NCH][B_TOT][N_OUT] = 32*32*1024 floats = 4 MB.
// __device__ global (no runtime allocation — harness allocation guards).
__device__ float g_partial[NCH * B_TOT * N_OUT];

__global__ __launch_bounds__(TPB)
void synapses_partial_kernel(const float* __restrict__ spikes,
                             const float* __restrict__ mem,
                             const float* __restrict__ rev,
                             const float* __restrict__ syn,
                             const float* __restrict__ W)
{
    const float decay = 1.0f - 1.0f / 5.0f;   // TAU = 5

    const int ic = blockIdx.x;          // i-chunk index
    const int bg = blockIdx.y;          // batch-group index
    const int i0 = ic * CHUNK;
    const int b0 = bg * BG;
    const int o4 = threadIdx.x;         // float4 index along o; o = 4*o4

    // Preload the per-(b,i) scalars for this chunk into shared memory.
    __shared__ float s_rev[BG][CHUNK];
    __shared__ float s_spk[BG][CHUNK];
    {
        int t = threadIdx.x;
        if (t < BG * CHUNK) {                       // 128 threads load rev
            int b = t / CHUNK, ii = t % CHUNK;
            s_rev[b][ii] = rev[(b0 + b) * N_IN + i0 + ii];
        } else if (t < 2 * BG * CHUNK) {            // next 128 load spikes
            int u = t - BG * CHUNK;
            int b = u / CHUNK, ii = u % CHUNK;
            s_spk[b][ii] = spikes[(b0 + b) * N_IN + i0 + ii];
        }
    }
    __syncthreads();

    float4 a1[BG];   // sum_i u * rev
    float4 a2[BG];   // sum_i u
#pragma unroll
    for (int b = 0; b < BG; b++) {
        a1[b] = make_float4(0.f, 0.f, 0.f, 0.f);
        a2[b] = make_float4(0.f, 0.f, 0.f, 0.f);
    }

    const float4* __restrict__ Wv = reinterpret_cast<const float4*>(W);
    const float4* __restrict__ Sv = reinterpret_cast<const float4*>(syn);
    const int row4 = N_OUT / 4;   // float4's per row = 256

#pragma unroll 2
    for (int ii = 0; ii < CHUNK; ii++) {
        const int i = i0 + ii;
        // Batch all loads first so ptxas front-batches them (MLP >= 5/warp,
        // >= 10 with the unroll-2) — DRAM latency must be MLP-hidden.
        const float4 w = __ldg(&Wv[i * row4 + o4]);
        float4 s[BG];
#pragma unroll
        for (int b = 0; b < BG; b++) {
            // syn is a pure 128MB stream: evict-first keeps W L2-resident.
            s[b] = __ldcs(&Sv[((b0 + b) * N_IN + i) * row4 + o4]);
        }
#pragma unroll
        for (int b = 0; b < BG; b++) {
            const float spk = s_spk[b][ii];
            const float rv  = s_rev[b][ii];

            const float ux = fmaf(s[b].x, decay, spk) * w.x;
            const float uy = fmaf(s[b].y, decay, spk) * w.y;
            const float uz = fmaf(s[b].z, decay, spk) * w.z;
            const float uw = fmaf(s[b].w, decay, spk) * w.w;

            a1[b].x = fmaf(ux, rv, a1[b].x);  a2[b].x += ux;
            a1[b].y = fmaf(uy, rv, a1[b].y);  a2[b].y += uy;
            a1[b].z = fmaf(uz, rv, a1[b].z);  a2[b].z += uz;
            a1[b].w = fmaf(uw, rv, a1[b].w);  a2[b].w += uw;
        }
    }

    // Per-chunk partial: a1 - mem * a2  (sums exactly to the reference over chunks).
    // Deterministic: fixed loop order per thread, plain stores (no atomics).
    // Default store policy (L2-allocating) so the reduce pass hits L2, not DRAM.
#pragma unroll
    for (int b = 0; b < BG; b++) {
        const int base = (b0 + b) * N_OUT + 4 * o4;
        const float4 m = *reinterpret_cast<const float4*>(&mem[base]);
        float4 p;
        p.x = a1[b].x - m.x * a2[b].x;
        p.y = a1[b].y - m.y * a2[b].y;
        p.z = a1[b].z - m.z * a2[b].z;
        p.w = a1[b].w - m.w * a2[b].w;
        *reinterpret_cast<float4*>(&g_partial[ic * (B_TOT * N_OUT) + base]) = p;
    }
}

// Fixed-order vectorized reduction over the NCH chunk partials:
// out[b,o] = sum_ic partial[ic][b][o]. Deterministic (fixed summation order).
// Partials are L2-hot (4 MB just written) -> this pass is L2-bandwidth bound.
__global__ __launch_bounds__(TPB)
void synapses_reduce_kernel(float* __restrict__ out, int n4)
{
    int idx = blockIdx.x * blockDim.x + threadIdx.x;   // float4 index over B*N_OUT/4
    if (idx >= n4) return;
    const float4* __restrict__ Pv = reinterpret_cast<const float4*>(g_partial);
    const int stride4 = (B_TOT * N_OUT) / 4;
    float4 acc = make_float4(0.f, 0.f, 0.f, 0.f);
#pragma unroll
    for (int ic = 0; ic < NCH; ic++) {
        const float4 p = __ldg(&Pv[ic * stride4 + idx]);   // L2 hit expected
        acc.x += p.x;  acc.y += p.y;  acc.z += p.z;  acc.w += p.w;
    }
    reinterpret_cast<float4*>(out)[idx] = acc;
}

extern "C" void kernel_launch(void* const* d_in, const int* in_sizes, int n_in,
                              void* d_out, int out_size)
{
    // Identify tensors robustly: syn and weights by unique sizes,
    // the three [B, N] tensors by declaration order (in_spikes, mem, rev).
    const float* spikes = nullptr;
    const float* mem    = nullptr;
    const float* rev    = nullptr;
    const float* syn    = nullptr;
    const float* W      = nullptr;

    int small_seen = 0;
    for (int i = 0; i < n_in; i++) {
        const float* p = (const float*)d_in[i];
        if (in_sizes[i] == B_TOT * N_IN * N_OUT) {
            syn = p;
        } else if (in_sizes[i] == N_IN * N_OUT) {
            W = p;
        } else {  // 32768-element tensors in order: in_spikes, mem, rev
            if      (small_seen == 0) spikes = p;
            else if (small_seen == 1) mem    = p;
            else                      rev    = p;
            small_seen++;
        }
    }

    float* out = (float*)d_out;

    dim3 grid(NCH, BGRP);   // 32 x 8 = 256 blocks
    synapses_partial_kernel<<<grid, TPB>>>(spikes, mem, rev, syn, W);

    const int n4 = out_size / 4;   // 8192 float4's
    synapses_reduce_kernel<<<(n4 + TPB - 1) / TPB, TPB>>>(out, n4);
}

// round 11
// speedup vs baseline: 1.0217x; 1.0217x over previous
#include <cuda_runtime.h>

// Problem constants
#define N_IN   1024
#define N_OUT  1024
#define B_TOT  32
#define TPB    256            // threads per block; each thread owns 4 consecutive o's
#define NCH    32             // number of i-chunks (grid sized for HBM saturation: 256 CTAs)
#define CHUNK  (N_IN / NCH)   // 32 i's per chunk
#define BG     4              // batches per block (W register reuse across batches)
#define BGRP   (B_TOT / BG)   // 8 batch groups

// Diagnostic no-op: pads the launch sequence to period 4 so ncu's "-s 5 -c 1"
// lands on the MAIN kernel (index 5 mod 4 == 1 in [zero, MAIN, noop, noop]).
// R8 evidence: with period 2 the capture landed on the reduce kernel.
// Removed once the main-kernel profile is in hand.
__global__ void noop_kernel() {}

// Vectorized zero-init of the output (it is poisoned 0xAA before timing and we
// accumulate into it with atomics).
__global__ void zero_out_kernel(float4* __restrict__ out, int n4) {
    int i = blockIdx.x * blockDim.x + threadIdx.x;
    if (i < n4) out[i] = make_float4(0.f, 0.f, 0.f, 0.f);
}

__global__ __launch_bounds__(TPB)
void synapses_partial_kernel(const float* __restrict__ spikes,
                             const float* __restrict__ mem,
                             const float* __restrict__ rev,
                             const float* __restrict__ syn,
                             const float* __restrict__ W,
                             float* __restrict__ out)
{
    const float decay = 1.0f - 1.0f / 5.0f;   // TAU = 5

    const int ic = blockIdx.x;          // i-chunk index
    const int bg = blockIdx.y;          // batch-group index
    const int i0 = ic * CHUNK;
    const int b0 = bg * BG;
    const int o4 = threadIdx.x;         // float4 index along o; o = 4*o4

    // Preload the per-(b,i) scalars for this chunk into shared memory.
    __shared__ float s_rev[BG][CHUNK];
    __shared__ float s_spk[BG][CHUNK];
    {
        int t = threadIdx.x;
        if (t < BG * CHUNK) {                       // 128 threads load rev
            int b = t / CHUNK, ii = t % CHUNK;
            s_rev[b][ii] = rev[(b0 + b) * N_IN + i0 + ii];
        } else if (t < 2 * BG * CHUNK) {            // next 128 load spikes
            int u = t - BG * CHUNK;
            int b = u / CHUNK, ii = u % CHUNK;
            s_spk[b][ii] = spikes[(b0 + b) * N_IN + i0 + ii];
        }
    }
    __syncthreads();

    float4 a1[BG];   // sum_i u * rev
    float4 a2[BG];   // sum_i u
#pragma unroll
    for (int b = 0; b < BG; b++) {
        a1[b] = make_float4(0.f, 0.f, 0.f, 0.f);
        a2[b] = make_float4(0.f, 0.f, 0.f, 0.f);
    }

    const float4* __restrict__ Wv = reinterpret_cast<const float4*>(W);
    const float4* __restrict__ Sv = reinterpret_cast<const float4*>(syn);
    const int row4 = N_OUT / 4;   // float4's per row = 256

#pragma unroll 2
    for (int ii = 0; ii < CHUNK; ii++) {
        const int i = i0 + ii;
        // Batch all loads first so ptxas front-batches them (MLP >= 5/warp,
        // >= 10 with the unroll-2) — DRAM latency must be MLP-hidden.
        const float4 w = __ldg(&Wv[i * row4 + o4]);
        float4 s[BG];
#pragma unroll
        for (int b = 0; b < BG; b++) {
            // syn is a pure 128MB stream: evict-first keeps W L2-resident.
            s[b] = __ldcs(&Sv[((b0 + b) * N_IN + i) * row4 + o4]);
        }
#pragma unroll
        for (int b = 0; b < BG; b++) {
            const float spk = s_spk[b][ii];
            const float rv  = s_rev[b][ii];

            const float ux = fmaf(s[b].x, decay, spk) * w.x;
            const float uy = fmaf(s[b].y, decay, spk) * w.y;
            const float uz = fmaf(s[b].z, decay, spk) * w.z;
            const float uw = fmaf(s[b].w, decay, spk) * w.w;

            a1[b].x = fmaf(ux, rv, a1[b].x);  a2[b].x += ux;
            a1[b].y = fmaf(uy, rv, a1[b].y);  a2[b].y += uy;
            a1[b].z = fmaf(uz, rv, a1[b].z);  a2[b].z += uz;
            a1[b].w = fmaf(uw, rv, a1[b].w);  a2[b].w += uw;
        }
    }

    // Per-chunk contribution: a1 - mem*a2, accumulated straight into out with
    // REDG atomics (spread addresses -> parallel across LTS partitions).
    // R8 post-mortem: the deterministic partial-buffer round-trip cost 7.9us
    // (DRAM-resident partials + latency-bound 32-CTA reduce). Validation is
    // rel_err < 1e-3; fp32 atomic-order variance is ~1e-7 relative -> safe.
#pragma unroll
    for (int b = 0; b < BG; b++) {
        const int base = (b0 + b) * N_OUT + 4 * o4;
        const float4 m = *reinterpret_cast<const float4*>(&mem[base]);
        float* op = &out[base];
        atomicAdd(op + 0, a1[b].x - m.x * a2[b].x);
        atomicAdd(op + 1, a1[b].y - m.y * a2[b].y);
        atomicAdd(op + 2, a1[b].z - m.z * a2[b].z);
        atomicAdd(op + 3, a1[b].w - m.w * a2[b].w);
    }
}

extern "C" void kernel_launch(void* const* d_in, const int* in_sizes, int n_in,
                              void* d_out, int out_size)
{
    // Identify tensors: syn and weights by unique sizes, the three [B, N]
    // tensors by declaration order (in_spikes, mem, rev).
    const float* spikes = nullptr;
    const float* mem    = nullptr;
    const float* rev    = nullptr;
    const float* syn    = nullptr;
    const float* W      = nullptr;

    int small_seen = 0;
    for (int i = 0; i < n_in; i++) {
        const float* p = (const float*)d_in[i];
        if (in_sizes[i] == B_TOT * N_IN * N_OUT) {
            syn = p;
        } else if (in_sizes[i] == N_IN * N_OUT) {
            W = p;
        } else {  // 32768-element tensors in order: in_spikes, mem, rev
            if      (small_seen == 0) spikes = p;
            else if (small_seen == 1) mem    = p;
            else                      rev    = p;
            small_seen++;
        }
    }

    float* out = (float*)d_out;
    const int n4 = out_size / 4;   // 8192 float4's

    // Period-4 launch pattern [zero, MAIN, noop, noop]: ncu (-s 5 -c 1)
    // profiles the MAIN kernel this round (launch index 5 mod 4 == 1).
    zero_out_kernel<<<(n4 + TPB - 1) / TPB, TPB>>>(reinterpret_cast<float4*>(out), n4);

    dim3 grid(NCH, BGRP);   // 32 x 8 = 256 blocks, all resident
    synapses_partial_kernel<<<grid, TPB>>>(spikes, mem, rev, syn, W, out);

    noop_kernel<<<1, 32>>>();
    noop_kernel<<<1, 32>>>();
}

// round 16
// speedup vs baseline: 1.0908x; 1.0677x over previous
#include <cuda_runtime.h>

// Problem constants
#define N_IN   1024
#define N_OUT  1024
#define B_TOT  32
#define TPB    256            // threads per block; each thread owns 4 consecutive o's
#define NCH    32             // number of i-chunks (grid sized for HBM saturation: 256 CTAs)
#define CHUNK  (N_IN / NCH)   // 32 i's per chunk
#define BG     4              // batches per block (W register reuse across batches)
#define BGRP   (B_TOT / BG)   // 8 batch groups

// Vectorized zero-init of the output (it is poisoned 0xAA before timing and we
// accumulate into it with atomics).
__global__ void zero_out_kernel(float4* __restrict__ out, int n4) {
    int i = blockIdx.x * blockDim.x + threadIdx.x;
    if (i < n4) out[i] = make_float4(0.f, 0.f, 0.f, 0.f);
}

__global__ __launch_bounds__(TPB)
void synapses_partial_kernel(const float* __restrict__ spikes,
                             const float* __restrict__ mem,
                             const float* __restrict__ rev,
                             const float* __restrict__ syn,
                             const float* __restrict__ W,
                             float* __restrict__ out)
{
    const float decay = 1.0f - 1.0f / 5.0f;   // TAU = 5

    const int ic = blockIdx.x;          // i-chunk index
    const int bg = blockIdx.y;          // batch-group index
    const int i0 = ic * CHUNK;
    const int b0 = bg * BG;
    const int o4 = threadIdx.x;         // float4 index along o; o = 4*o4

    // Preload the per-(b,i) scalars for this chunk into shared memory.
    __shared__ float s_rev[BG][CHUNK];
    __shared__ float s_spk[BG][CHUNK];
    {
        int t = threadIdx.x;
        if (t < BG * CHUNK) {                       // 128 threads load rev
            int b = t / CHUNK, ii = t % CHUNK;
            s_rev[b][ii] = rev[(b0 + b) * N_IN + i0 + ii];
        } else if (t < 2 * BG * CHUNK) {            // next 128 load spikes
            int u = t - BG * CHUNK;
            int b = u / CHUNK, ii = u % CHUNK;
            s_spk[b][ii] = spikes[(b0 + b) * N_IN + i0 + ii];
        }
    }
    __syncthreads();

    float4 a1[BG];   // sum_i u * rev
    float4 a2[BG];   // sum_i u
#pragma unroll
    for (int b = 0; b < BG; b++) {
        a1[b] = make_float4(0.f, 0.f, 0.f, 0.f);
        a2[b] = make_float4(0.f, 0.f, 0.f, 0.f);
    }

    const float4* __restrict__ Wv = reinterpret_cast<const float4*>(W);
    const float4* __restrict__ Sv = reinterpret_cast<const float4*>(syn);
    const int row4 = N_OUT / 4;   // float4's per row = 256

#pragma unroll 2
    for (int ii = 0; ii < CHUNK; ii++) {
        const int i = i0 + ii;
        // Batch all loads first so ptxas front-batches them (MLP >= 5/warp,
        // >= 10 with the unroll-2) — DRAM latency must be MLP-hidden.
        const float4 w = __ldg(&Wv[i * row4 + o4]);
        float4 s[BG];
#pragma unroll
        for (int b = 0; b < BG; b++) {
            // syn is a pure 128MB stream: evict-first keeps W L2-resident.
            s[b] = __ldcs(&Sv[((b0 + b) * N_IN + i) * row4 + o4]);
        }
#pragma unroll
        for (int b = 0; b < BG; b++) {
            const float spk = s_spk[b][ii];
            const float rv  = s_rev[b][ii];

            const float ux = fmaf(s[b].x, decay, spk) * w.x;
            const float uy = fmaf(s[b].y, decay, spk) * w.y;
            const float uz = fmaf(s[b].z, decay, spk) * w.z;
            const float uw = fmaf(s[b].w, decay, spk) * w.w;

            a1[b].x = fmaf(ux, rv, a1[b].x);  a2[b].x += ux;
            a1[b].y = fmaf(uy, rv, a1[b].y);  a2[b].y += uy;
            a1[b].z = fmaf(uz, rv, a1[b].z);  a2[b].z += uz;
            a1[b].w = fmaf(uw, rv, a1[b].w);  a2[b].w += uw;
        }
    }

    // Per-chunk contribution: a1 - mem*a2, accumulated straight into out with
    // REDG atomics (spread addresses -> parallel across LTS partitions).
    // Validation is rel_err < 1e-3; fp32 atomic-order variance ~1e-7 -> safe.
#pragma unroll
    for (int b = 0; b < BG; b++) {
        const int base = (b0 + b) * N_OUT + 4 * o4;
        const float4 m = *reinterpret_cast<const float4*>(&mem[base]);
        float* op = &out[base];
        atomicAdd(op + 0, a1[b].x - m.x * a2[b].x);
        atomicAdd(op + 1, a1[b].y - m.y * a2[b].y);
        atomicAdd(op + 2, a1[b].z - m.z * a2[b].z);
        atomicAdd(op + 3, a1[b].w - m.w * a2[b].w);
    }
}

extern "C" void kernel_launch(void* const* d_in, const int* in_sizes, int n_in,
                              void* d_out, int out_size)
{
    // Identify tensors: syn and weights by unique sizes, the three [B, N]
    // tensors by declaration order (in_spikes, mem, rev).
    const float* spikes = nullptr;
    const float* mem    = nullptr;
    const float* rev    = nullptr;
    const float* syn    = nullptr;
    const float* W      = nullptr;

    int small_seen = 0;
    for (int i = 0; i < n_in; i++) {
        const float* p = (const float*)d_in[i];
        if (in_sizes[i] == B_TOT * N_IN * N_OUT) {
            syn = p;
        } else if (in_sizes[i] == N_IN * N_OUT) {
            W = p;
        } else {  // 32768-element tensors in order: in_spikes, mem, rev
            if      (small_seen == 0) spikes = p;
            else if (small_seen == 1) mem    = p;
            else                      rev    = p;
            small_seen++;
        }
    }

    float* out = (float*)d_out;
    const int n4 = out_size / 4;   // 8192 float4's

    // Period-2 sequence [zero, MAIN]. R8 evidence: ncu's "-s 5 -c 1" capture
    // lands on the ODD launch position -> profiles MAIN this round.
    zero_out_kernel<<<(n4 + TPB - 1) / TPB, TPB>>>(reinterpret_cast<float4*>(out), n4);

    dim3 grid(NCH, BGRP);   // 32 x 8 = 256 blocks, all resident
    synapses_partial_kernel<<<grid, TPB>>>(spikes, mem, rev, syn, W, out);
}